// round 6
// baseline (speedup 1.0000x reference)
#include <cuda_runtime.h>
#include <cstdint>

#define D    128
#define OUTD 128
#define NDST_MAX 20000

// Scratch (no allocations allowed)
__device__ float g_agg[NDST_MAX * D];
__device__ float g_deg[NDST_MAX];
__device__ int   g_is64;

// ---------------------------------------------------------------------------
// Detect whether edge indices are int64 or int32 (jax x64-flag ambiguity).
// If int64: every value < 100000 => high 32-bit word of each element is 0.
// If int32: the "high words" are the next edge values -> almost surely nonzero.
// Reads only the first 64 int32 words (in-bounds for either dtype, E >= 64).
// ---------------------------------------------------------------------------
__global__ void detect_kernel(const int* __restrict__ words, int n_words) {
    if (blockIdx.x == 0 && threadIdx.x == 0) {
        int pairs = n_words / 2;
        if (pairs > 32) pairs = 32;
        int is64 = 1;
        for (int i = 0; i < pairs; i++) {
            if (words[2 * i + 1] != 0) { is64 = 0; break; }
        }
        g_is64 = is64;
    }
}

// ---------------------------------------------------------------------------
// Zero agg + deg
// ---------------------------------------------------------------------------
__global__ void zero_kernel(int n_dst) {
    int i = blockIdx.x * blockDim.x + threadIdx.x;
    int total = n_dst * D;
    int stride = gridDim.x * blockDim.x;
    for (int idx = i; idx < total; idx += stride) g_agg[idx] = 0.0f;
    for (int idx = i; idx < n_dst; idx += stride) g_deg[idx] = 0.0f;
}

// ---------------------------------------------------------------------------
// Edge scatter: one warp per edge. Each lane moves 4 floats (float4 gather,
// red.global.add.v4.f32 scatter). Lane 0 bumps the degree counter.
// ---------------------------------------------------------------------------
__global__ void scatter_kernel(const float* __restrict__ h,
                               const void* __restrict__ es,
                               const void* __restrict__ ed,
                               int E) {
    int gtid = blockIdx.x * blockDim.x + threadIdx.x;
    int e    = gtid >> 5;
    int lane = threadIdx.x & 31;
    if (e >= E) return;

    long long s, d;
    if (g_is64) {
        s = ((const long long*)es)[e];
        d = ((const long long*)ed)[e];
    } else {
        s = ((const int*)es)[e];
        d = ((const int*)ed)[e];
    }

    float4 v = *(const float4*)(h + (size_t)s * D + lane * 4);
    float* dst = g_agg + (size_t)d * D + lane * 4;
    asm volatile("red.global.add.v4.f32 [%0], {%1, %2, %3, %4};"
                 :: "l"(dst), "f"(v.x), "f"(v.y), "f"(v.z), "f"(v.w)
                 : "memory");
    if (lane == 0) atomicAdd(&g_deg[d], 1.0f);
}

// ---------------------------------------------------------------------------
// Fused mean + concat + GEMM + bias + relu.
// Tile: 32 dst rows x 128 outputs per CTA (256 threads, 4x4 register tile).
// SMEM: W transposed [256][132] (pad vs conflicts) = 132KB,
//       Z transposed [256][40]  (pad, 16B aligned)  =  40KB.
// ---------------------------------------------------------------------------
#define SW_STRIDE 132
#define SZ_STRIDE 40
#define SMEM_FLOATS (256 * SW_STRIDE + 256 * SZ_STRIDE)

__global__ void gemm_kernel(const float* __restrict__ h,
                            const float* __restrict__ W,
                            const float* __restrict__ b,
                            float* __restrict__ out,
                            int n_dst) {
    extern __shared__ float smem[];
    float* sW = smem;                    // [k][n], k<256, n<128
    float* sZ = smem + 256 * SW_STRIDE;  // [k][m], k<256, m<32

    int tid  = threadIdx.x;
    int row0 = blockIdx.x * 32;

    // Load W transposed into SMEM: sW[k][n] = W[n*256 + k]
    // consecutive tid -> consecutive k (coalesced global read)
    for (int idx = tid; idx < OUTD * 2 * D; idx += 256) {
        int n = idx >> 8;
        int k = idx & 255;
        sW[k * SW_STRIDE + n] = W[idx];
    }

    // Build Z tile: z[m][k] = h[row][k] for k<128, agg[row][k-128]/max(deg,1)
    for (int idx = tid; idx < 32 * D; idx += 256) {
        int r = idx >> 7;
        int k = idx & 127;
        int row = row0 + r;
        float hv = 0.0f, av = 0.0f;
        if (row < n_dst) {
            hv = h[(size_t)row * D + k];
            float dv = g_deg[row];
            av = g_agg[(size_t)row * D + k] * (1.0f / fmaxf(dv, 1.0f));
        }
        sZ[k * SZ_STRIDE + r]         = hv;
        sZ[(k + 128) * SZ_STRIDE + r] = av;
    }
    __syncthreads();

    int m0 = (tid >> 5) * 4;   // 8 row groups of 4
    int n0 = (tid & 31) * 4;   // 32 col groups of 4

    float acc[4][4];
#pragma unroll
    for (int i = 0; i < 4; i++)
#pragma unroll
        for (int j = 0; j < 4; j++) acc[i][j] = 0.0f;

#pragma unroll 4
    for (int k = 0; k < 256; k++) {
        float4 z = *(const float4*)&sZ[k * SZ_STRIDE + m0];  // broadcast
        float4 w = *(const float4*)&sW[k * SW_STRIDE + n0];  // conflict-free
        acc[0][0] += z.x * w.x; acc[0][1] += z.x * w.y; acc[0][2] += z.x * w.z; acc[0][3] += z.x * w.w;
        acc[1][0] += z.y * w.x; acc[1][1] += z.y * w.y; acc[1][2] += z.y * w.z; acc[1][3] += z.y * w.w;
        acc[2][0] += z.z * w.x; acc[2][1] += z.z * w.y; acc[2][2] += z.z * w.z; acc[2][3] += z.z * w.w;
        acc[3][0] += z.w * w.x; acc[3][1] += z.w * w.y; acc[3][2] += z.w * w.z; acc[3][3] += z.w * w.w;
    }

    float4 bv = *(const float4*)&b[n0];
#pragma unroll
    for (int i = 0; i < 4; i++) {
        int row = row0 + m0 + i;
        if (row < n_dst) {
            float4 o;
            o.x = fmaxf(acc[i][0] + bv.x, 0.0f);
            o.y = fmaxf(acc[i][1] + bv.y, 0.0f);
            o.z = fmaxf(acc[i][2] + bv.z, 0.0f);
            o.w = fmaxf(acc[i][3] + bv.w, 0.0f);
            *(float4*)&out[(size_t)row * OUTD + n0] = o;
        }
    }
}

// ---------------------------------------------------------------------------
// Inputs (metadata order): h[f32 NSRC*D], edge_src, edge_dst, W[f32 128*256],
// b[f32 128], n_dst(scalar, ignored; derived from out_size)
// ---------------------------------------------------------------------------
extern "C" void kernel_launch(void* const* d_in, const int* in_sizes, int n_in,
                              void* d_out, int out_size) {
    const float* h = (const float*)d_in[0];
    const void*  es = d_in[1];
    const void*  ed = d_in[2];
    const float* W = (const float*)d_in[3];
    const float* b = (const float*)d_in[4];
    float* out = (float*)d_out;

    int E     = in_sizes[1];
    int n_dst = out_size / OUTD;

    detect_kernel<<<1, 32>>>((const int*)es, E);

    int totz = n_dst * D;
    int zb = (totz + 1023) / 1024;
    zero_kernel<<<zb, 1024>>>(n_dst);

    long long sthreads = (long long)E * 32;
    int sblocks = (int)((sthreads + 255) / 256);
    scatter_kernel<<<sblocks, 256>>>(h, es, ed, E);

    const int smem_bytes = SMEM_FLOATS * 4;
    cudaFuncSetAttribute(gemm_kernel, cudaFuncAttributeMaxDynamicSharedMemorySize,
                         smem_bytes);
    gemm_kernel<<<(n_dst + 31) / 32, 256, smem_bytes>>>(h, W, b, out, n_dst);
}

// round 8
// speedup vs baseline: 1.0039x; 1.0039x over previous
#include <cuda_runtime.h>
#include <cstdint>

#define D    128
#define OUTD 128
#define NDST_MAX 20000

// Scratch (no allocations allowed)
__device__ float g_agg[NDST_MAX * D];
__device__ float g_deg[NDST_MAX];
__device__ int   g_is64;

// ---------------------------------------------------------------------------
// Detect whether edge indices are int64 or int32 (jax x64-flag ambiguity).
// If int64: every value < 100000 => high 32-bit word of each element is 0.
// If int32: the "high words" are the next edge values -> almost surely nonzero.
// Reads only the first 64 int32 words (in-bounds for either dtype, E >= 64).
// ---------------------------------------------------------------------------
__global__ void detect_kernel(const int* __restrict__ words, int n_words) {
    if (blockIdx.x == 0 && threadIdx.x == 0) {
        int pairs = n_words / 2;
        if (pairs > 32) pairs = 32;
        int is64 = 1;
        for (int i = 0; i < pairs; i++) {
            if (words[2 * i + 1] != 0) { is64 = 0; break; }
        }
        g_is64 = is64;
    }
}

// ---------------------------------------------------------------------------
// Zero agg + deg
// ---------------------------------------------------------------------------
__global__ void zero_kernel(int n_dst) {
    int i = blockIdx.x * blockDim.x + threadIdx.x;
    int total = n_dst * D;
    int stride = gridDim.x * blockDim.x;
    for (int idx = i; idx < total; idx += stride) g_agg[idx] = 0.0f;
    for (int idx = i; idx < n_dst; idx += stride) g_deg[idx] = 0.0f;
}

// ---------------------------------------------------------------------------
// Edge scatter: one warp per edge. Each lane moves 4 floats (float4 gather,
// red.global.add.v4.f32 scatter). Lane 0 bumps the degree counter.
// ---------------------------------------------------------------------------
__global__ void scatter_kernel(const float* __restrict__ h,
                               const void* __restrict__ es,
                               const void* __restrict__ ed,
                               int E) {
    int gtid = blockIdx.x * blockDim.x + threadIdx.x;
    int e    = gtid >> 5;
    int lane = threadIdx.x & 31;
    if (e >= E) return;

    long long s, d;
    if (g_is64) {
        s = ((const long long*)es)[e];
        d = ((const long long*)ed)[e];
    } else {
        s = ((const int*)es)[e];
        d = ((const int*)ed)[e];
    }

    float4 v = *(const float4*)(h + (size_t)s * D + lane * 4);
    float* dst = g_agg + (size_t)d * D + lane * 4;
    asm volatile("red.global.add.v4.f32 [%0], {%1, %2, %3, %4};"
                 :: "l"(dst), "f"(v.x), "f"(v.y), "f"(v.z), "f"(v.w)
                 : "memory");
    if (lane == 0) atomicAdd(&g_deg[d], 1.0f);
}

// ---------------------------------------------------------------------------
// Fused mean + concat + GEMM + bias + relu.
// Tile: 32 dst rows x 128 outputs per CTA (256 threads, 4x4 register tile).
// SMEM: W transposed [256][132] (pad vs conflicts) = 132KB,
//       Z transposed [256][40]  (pad, 16B aligned)  =  40KB.
// ---------------------------------------------------------------------------
#define SW_STRIDE 132
#define SZ_STRIDE 40
#define SMEM_FLOATS (256 * SW_STRIDE + 256 * SZ_STRIDE)

__global__ void gemm_kernel(const float* __restrict__ h,
                            const float* __restrict__ W,
                            const float* __restrict__ b,
                            float* __restrict__ out,
                            int n_dst) {
    extern __shared__ float smem[];
    float* sW = smem;                    // [k][n], k<256, n<128
    float* sZ = smem + 256 * SW_STRIDE;  // [k][m], k<256, m<32

    int tid  = threadIdx.x;
    int row0 = blockIdx.x * 32;

    // Load W transposed into SMEM: sW[k][n] = W[n*256 + k]
    // consecutive tid -> consecutive k (coalesced global read)
    for (int idx = tid; idx < OUTD * 2 * D; idx += 256) {
        int n = idx >> 8;
        int k = idx & 255;
        sW[k * SW_STRIDE + n] = W[idx];
    }

    // Build Z tile: z[m][k] = h[row][k] for k<128, agg[row][k-128]/max(deg,1)
    for (int idx = tid; idx < 32 * D; idx += 256) {
        int r = idx >> 7;
        int k = idx & 127;
        int row = row0 + r;
        float hv = 0.0f, av = 0.0f;
        if (row < n_dst) {
            hv = h[(size_t)row * D + k];
            float dv = g_deg[row];
            av = g_agg[(size_t)row * D + k] * (1.0f / fmaxf(dv, 1.0f));
        }
        sZ[k * SZ_STRIDE + r]         = hv;
        sZ[(k + 128) * SZ_STRIDE + r] = av;
    }
    __syncthreads();

    int m0 = (tid >> 5) * 4;   // 8 row groups of 4
    int n0 = (tid & 31) * 4;   // 32 col groups of 4

    float acc[4][4];
#pragma unroll
    for (int i = 0; i < 4; i++)
#pragma unroll
        for (int j = 0; j < 4; j++) acc[i][j] = 0.0f;

#pragma unroll 4
    for (int k = 0; k < 256; k++) {
        float4 z = *(const float4*)&sZ[k * SZ_STRIDE + m0];  // broadcast
        float4 w = *(const float4*)&sW[k * SW_STRIDE + n0];  // conflict-free
        acc[0][0] += z.x * w.x; acc[0][1] += z.x * w.y; acc[0][2] += z.x * w.z; acc[0][3] += z.x * w.w;
        acc[1][0] += z.y * w.x; acc[1][1] += z.y * w.y; acc[1][2] += z.y * w.z; acc[1][3] += z.y * w.w;
        acc[2][0] += z.z * w.x; acc[2][1] += z.z * w.y; acc[2][2] += z.z * w.z; acc[2][3] += z.z * w.w;
        acc[3][0] += z.w * w.x; acc[3][1] += z.w * w.y; acc[3][2] += z.w * w.z; acc[3][3] += z.w * w.w;
    }

    float4 bv = *(const float4*)&b[n0];
#pragma unroll
    for (int i = 0; i < 4; i++) {
        int row = row0 + m0 + i;
        if (row < n_dst) {
            float4 o;
            o.x = fmaxf(acc[i][0] + bv.x, 0.0f);
            o.y = fmaxf(acc[i][1] + bv.y, 0.0f);
            o.z = fmaxf(acc[i][2] + bv.z, 0.0f);
            o.w = fmaxf(acc[i][3] + bv.w, 0.0f);
            *(float4*)&out[(size_t)row * OUTD + n0] = o;
        }
    }
}

// ---------------------------------------------------------------------------
// Inputs (metadata order): h[f32 NSRC*D], edge_src, edge_dst, W[f32 128*256],
// b[f32 128], n_dst(scalar, ignored; derived from out_size)
// ---------------------------------------------------------------------------
extern "C" void kernel_launch(void* const* d_in, const int* in_sizes, int n_in,
                              void* d_out, int out_size) {
    const float* h = (const float*)d_in[0];
    const void*  es = d_in[1];
    const void*  ed = d_in[2];
    const float* W = (const float*)d_in[3];
    const float* b = (const float*)d_in[4];
    float* out = (float*)d_out;

    int E     = in_sizes[1];
    int n_dst = out_size / OUTD;

    detect_kernel<<<1, 32>>>((const int*)es, E);

    int totz = n_dst * D;
    int zb = (totz + 1023) / 1024;
    zero_kernel<<<zb, 1024>>>(n_dst);

    long long sthreads = (long long)E * 32;
    int sblocks = (int)((sthreads + 255) / 256);
    scatter_kernel<<<sblocks, 256>>>(h, es, ed, E);

    const int smem_bytes = SMEM_FLOATS * 4;
    cudaFuncSetAttribute(gemm_kernel, cudaFuncAttributeMaxDynamicSharedMemorySize,
                         smem_bytes);
    gemm_kernel<<<(n_dst + 31) / 32, 256, smem_bytes>>>(h, W, b, out, n_dst);
}